// round 1
// baseline (speedup 1.0000x reference)
#include <cuda_runtime.h>
#include <math.h>
#include <stdint.h>

// Problem constants
#define SEQ   2048
#define DM    1024
#define NH    16
#define DK    64
#define DFF   4096
#define NL    4
#define LN_EPS 1e-5f

// ---------------------------------------------------------------------------
// Scratch (static device globals: allocation-free kernel_launch)
// ---------------------------------------------------------------------------
__device__ float g_x[SEQ * DM];
__device__ float g_q[SEQ * DM];   // also reused as ctx
__device__ float g_k[SEQ * DM];
__device__ float g_v[SEQ * DM];
__device__ float g_t[SEQ * DM];   // attn_out / ffn_out
__device__ float g_h[SEQ * DFF];
__device__ float g_s[(size_t)NH * SEQ * SEQ];   // attention scores, 256 MB

// ---------------------------------------------------------------------------
// Generic tiled fp32 GEMM:
//   C[z] = act( alpha * A[z] @ (B[z] or B[z]^T) + bias )
// A: [M,K] row-major (lda), B: [K,N] rm (NN) or [N,K] rm (NT), C: [M,N] (ldc)
// Per-z (head) strides in elements. All dims assumed multiples of tile sizes
// (true for every call site here).
// ---------------------------------------------------------------------------
template<int BM, int BN, int BK, int TM, int TN, bool TRANSB, int ACT>
__global__ __launch_bounds__(256)
void gemm_k(const float* __restrict__ Ag, const float* __restrict__ Bg,
            const float* __restrict__ bias, float* __restrict__ Cg,
            int M, int N, int K, int lda, int ldb, int ldc,
            size_t sA, size_t sB, size_t sC, float alpha)
{
    constexpr int NT_ = (BM / TM) * (BN / TN);   // threads per block (=256)
    const int tid = threadIdx.x;
    const int bm0 = blockIdx.y * BM;
    const int bn0 = blockIdx.x * BN;
    const float* A = Ag + (size_t)blockIdx.z * sA;
    const float* B = Bg + (size_t)blockIdx.z * sB;
    float*       C = Cg + (size_t)blockIdx.z * sC;

    __shared__ float As[BK][BM];
    __shared__ float Bs[BK][BN];

    const int tx = tid % (BN / TN);
    const int ty = tid / (BN / TN);

    float acc[TM][TN];
#pragma unroll
    for (int i = 0; i < TM; i++)
#pragma unroll
        for (int j = 0; j < TN; j++) acc[i][j] = 0.f;

    for (int k0 = 0; k0 < K; k0 += BK) {
        // ---- load A tile (BM x BK), store transposed As[k][m]
#pragma unroll
        for (int t = tid; t < BM * BK / 4; t += NT_) {
            int row = t / (BK / 4), kv = t % (BK / 4);
            float4 a4 = *(const float4*)&A[(size_t)(bm0 + row) * lda + k0 + kv * 4];
            As[kv * 4 + 0][row] = a4.x;
            As[kv * 4 + 1][row] = a4.y;
            As[kv * 4 + 2][row] = a4.z;
            As[kv * 4 + 3][row] = a4.w;
        }
        // ---- load B tile
        if (!TRANSB) {
#pragma unroll
            for (int t = tid; t < BK * BN / 4; t += NT_) {
                int row = t / (BN / 4), cv = t % (BN / 4);
                float4 b4 = *(const float4*)&B[(size_t)(k0 + row) * ldb + bn0 + cv * 4];
                *(float4*)&Bs[row][cv * 4] = b4;
            }
        } else {
#pragma unroll
            for (int t = tid; t < BN * BK / 4; t += NT_) {
                int n = t / (BK / 4), kv = t % (BK / 4);
                float4 b4 = *(const float4*)&B[(size_t)(bn0 + n) * ldb + k0 + kv * 4];
                Bs[kv * 4 + 0][n] = b4.x;
                Bs[kv * 4 + 1][n] = b4.y;
                Bs[kv * 4 + 2][n] = b4.z;
                Bs[kv * 4 + 3][n] = b4.w;
            }
        }
        __syncthreads();

#pragma unroll
        for (int kk = 0; kk < BK; kk++) {
            float ar[TM], br[TN];
#pragma unroll
            for (int i = 0; i < TM; i += 4)
                *(float4*)&ar[i] = *(const float4*)&As[kk][ty * TM + i];
#pragma unroll
            for (int j = 0; j < TN; j += 4)
                *(float4*)&br[j] = *(const float4*)&Bs[kk][tx * TN + j];
#pragma unroll
            for (int i = 0; i < TM; i++)
#pragma unroll
                for (int j = 0; j < TN; j++)
                    acc[i][j] = fmaf(ar[i], br[j], acc[i][j]);
        }
        __syncthreads();
    }

    // ---- epilogue
#pragma unroll
    for (int i = 0; i < TM; i++) {
        int r = bm0 + ty * TM + i;
#pragma unroll
        for (int j = 0; j < TN; j++) {
            int c = bn0 + tx * TN + j;
            float v = acc[i][j] * alpha;
            if (bias != nullptr) v += bias[c];
            if (ACT == 1) {   // tanh-approx gelu (matches jax.nn.gelu default)
                float xx = v;
                float tt = tanhf(0.7978845608028654f * (xx + 0.044715f * xx * xx * xx));
                v = 0.5f * xx * (1.f + tt);
            }
            C[(size_t)r * ldc + c] = v;
        }
    }
}

// ---------------------------------------------------------------------------
// Softmax over rows of length 2048 (register-resident, 1 read + 1 write)
// ---------------------------------------------------------------------------
__global__ __launch_bounds__(256)
void softmax2048_k(float* __restrict__ data)
{
    const int tid = threadIdx.x;
    float4* p4 = (float4*)(data + (size_t)blockIdx.x * 2048);
    float4 a = p4[tid];
    float4 b = p4[tid + 256];

    __shared__ float red[256];

    float m = fmaxf(fmaxf(fmaxf(a.x, a.y), fmaxf(a.z, a.w)),
                    fmaxf(fmaxf(b.x, b.y), fmaxf(b.z, b.w)));
    red[tid] = m; __syncthreads();
#pragma unroll
    for (int s = 128; s > 0; s >>= 1) {
        if (tid < s) red[tid] = fmaxf(red[tid], red[tid + s]);
        __syncthreads();
    }
    m = red[0];
    __syncthreads();

    a.x = __expf(a.x - m); a.y = __expf(a.y - m);
    a.z = __expf(a.z - m); a.w = __expf(a.w - m);
    b.x = __expf(b.x - m); b.y = __expf(b.y - m);
    b.z = __expf(b.z - m); b.w = __expf(b.w - m);

    float sum = a.x + a.y + a.z + a.w + b.x + b.y + b.z + b.w;
    red[tid] = sum; __syncthreads();
#pragma unroll
    for (int s = 128; s > 0; s >>= 1) {
        if (tid < s) red[tid] += red[tid + s];
        __syncthreads();
    }
    float inv = 1.0f / red[0];

    a.x *= inv; a.y *= inv; a.z *= inv; a.w *= inv;
    b.x *= inv; b.y *= inv; b.z *= inv; b.w *= inv;
    p4[tid] = a;
    p4[tid + 256] = b;
}

// ---------------------------------------------------------------------------
// Fused residual + LayerNorm over rows of 1024: out = LN(x + sub) * g + b
// Safe in-place (out == x): row fully register-resident before writes.
// ---------------------------------------------------------------------------
__global__ __launch_bounds__(256)
void ln_k(const float* __restrict__ x, const float* __restrict__ sub,
          const float* __restrict__ g, const float* __restrict__ b,
          float* __restrict__ out)
{
    const int tid = threadIdx.x;
    const size_t base = (size_t)blockIdx.x * DM + tid * 4;

    float4 xv = *(const float4*)(x + base);
    float4 sv = *(const float4*)(sub + base);
    float v0 = xv.x + sv.x, v1 = xv.y + sv.y, v2 = xv.z + sv.z, v3 = xv.w + sv.w;

    __shared__ float red[256];
    red[tid] = v0 + v1 + v2 + v3; __syncthreads();
#pragma unroll
    for (int s = 128; s > 0; s >>= 1) {
        if (tid < s) red[tid] += red[tid + s];
        __syncthreads();
    }
    const float mu = red[0] * (1.f / DM);
    __syncthreads();

    const float d0 = v0 - mu, d1 = v1 - mu, d2 = v2 - mu, d3 = v3 - mu;
    red[tid] = d0 * d0 + d1 * d1 + d2 * d2 + d3 * d3; __syncthreads();
#pragma unroll
    for (int s = 128; s > 0; s >>= 1) {
        if (tid < s) red[tid] += red[tid + s];
        __syncthreads();
    }
    const float inv = rsqrtf(red[0] * (1.f / DM) + LN_EPS);

    float4 gv = *(const float4*)(g + tid * 4);
    float4 bv = *(const float4*)(b + tid * 4);
    float4 o;
    o.x = d0 * inv * gv.x + bv.x;
    o.y = d1 * inv * gv.y + bv.y;
    o.z = d2 * inv * gv.z + bv.z;
    o.w = d3 * inv * gv.w + bv.w;
    *(float4*)(out + base) = o;
}

// ---------------------------------------------------------------------------
// Host launcher
// ---------------------------------------------------------------------------
extern "C" void kernel_launch(void* const* d_in, const int* in_sizes, int n_in,
                              void* d_out, int out_size)
{
    (void)in_sizes; (void)n_in; (void)out_size;

    const float* x_in = (const float*)d_in[0];
    const float* wq  = (const float*)d_in[1];
    const float* bq  = (const float*)d_in[2];
    const float* wk  = (const float*)d_in[3];
    const float* bk  = (const float*)d_in[4];
    const float* wv  = (const float*)d_in[5];
    const float* bv  = (const float*)d_in[6];
    const float* wo  = (const float*)d_in[7];
    const float* bo  = (const float*)d_in[8];
    const float* w1  = (const float*)d_in[9];
    const float* b1  = (const float*)d_in[10];
    const float* w2  = (const float*)d_in[11];
    const float* b2  = (const float*)d_in[12];
    const float* ln1g = (const float*)d_in[13];
    const float* ln1b = (const float*)d_in[14];
    const float* ln2g = (const float*)d_in[15];
    const float* ln2b = (const float*)d_in[16];

    float *x, *q, *k, *v, *t, *h, *s;
    cudaGetSymbolAddress((void**)&x, g_x);
    cudaGetSymbolAddress((void**)&q, g_q);
    cudaGetSymbolAddress((void**)&k, g_k);
    cudaGetSymbolAddress((void**)&v, g_v);
    cudaGetSymbolAddress((void**)&t, g_t);
    cudaGetSymbolAddress((void**)&h, g_h);
    cudaGetSymbolAddress((void**)&s, g_s);

    cudaMemcpyAsync(x, x_in, (size_t)SEQ * DM * sizeof(float),
                    cudaMemcpyDeviceToDevice, 0);

    for (int l = 0; l < NL; l++) {
        const float* Wq = wq + (size_t)l * DM * DM;
        const float* Wk = wk + (size_t)l * DM * DM;
        const float* Wv = wv + (size_t)l * DM * DM;
        const float* Wo = wo + (size_t)l * DM * DM;
        const float* W1 = w1 + (size_t)l * DM * DFF;
        const float* W2 = w2 + (size_t)l * DFF * DM;
        const float* Bq = bq + (size_t)l * DM;
        const float* Bk = bk + (size_t)l * DM;
        const float* Bv = bv + (size_t)l * DM;
        const float* Bo = bo + (size_t)l * DM;
        const float* B1 = b1 + (size_t)l * DFF;
        const float* B2 = b2 + (size_t)l * DM;
        const float* G1 = ln1g + (size_t)l * DM;
        const float* Be1 = ln1b + (size_t)l * DM;
        const float* G2 = ln2g + (size_t)l * DM;
        const float* Be2 = ln2b + (size_t)l * DM;

        dim3 gProj(DM / 128, SEQ / 128, 1);
        // Q, K, V projections
        gemm_k<128,128,8,8,8,false,0><<<gProj,256>>>(x, Wq, Bq, q, SEQ, DM, DM,
                                                     DM, DM, DM, 0, 0, 0, 1.f);
        gemm_k<128,128,8,8,8,false,0><<<gProj,256>>>(x, Wk, Bk, k, SEQ, DM, DM,
                                                     DM, DM, DM, 0, 0, 0, 1.f);
        gemm_k<128,128,8,8,8,false,0><<<gProj,256>>>(x, Wv, Bv, v, SEQ, DM, DM,
                                                     DM, DM, DM, 0, 0, 0, 1.f);
        // scores[h] = (Q_h @ K_h^T) / 8   (batched NT over heads)
        gemm_k<128,128,8,8,8,true,0><<<dim3(SEQ/128, SEQ/128, NH),256>>>(
            q, k, nullptr, s, SEQ, SEQ, DK,
            DM, DM, SEQ,
            (size_t)DK, (size_t)DK, (size_t)SEQ * SEQ, 0.125f);
        // softmax over last dim
        softmax2048_k<<<NH * SEQ, 256>>>(s);
        // ctx[h] = attn[h] @ V_h   (batched NN, N=64) -> reuse q buffer
        gemm_k<128,64,8,8,4,false,0><<<dim3(1, SEQ/128, NH),256>>>(
            s, v, nullptr, q, SEQ, DK, SEQ,
            SEQ, DM, DM,
            (size_t)SEQ * SEQ, (size_t)DK, (size_t)DK, 1.f);
        // attn_out = ctx @ Wo + bo
        gemm_k<128,128,8,8,8,false,0><<<gProj,256>>>(q, Wo, Bo, t, SEQ, DM, DM,
                                                     DM, DM, DM, 0, 0, 0, 1.f);
        // x = LN1(x + attn_out)
        ln_k<<<SEQ,256>>>(x, t, G1, Be1, x);
        // h = gelu(x @ W1 + b1)
        gemm_k<128,128,8,8,8,false,1><<<dim3(DFF/128, SEQ/128, 1),256>>>(
            x, W1, B1, h, SEQ, DFF, DM,
            DM, DFF, DFF, 0, 0, 0, 1.f);
        // ffn_out = h @ W2 + b2
        gemm_k<128,128,8,8,8,false,0><<<dim3(DM/128, SEQ/128, 1),256>>>(
            h, W2, B2, t, SEQ, DM, DFF,
            DFF, DM, DM, 0, 0, 0, 1.f);
        // x = LN2(x + ffn_out); final layer writes straight to d_out
        float* outp = (l == NL - 1) ? (float*)d_out : x;
        ln_k<<<SEQ,256>>>(x, t, G2, Be2, outp);
    }
}

// round 3
// speedup vs baseline: 3.1491x; 3.1491x over previous
#include <cuda_runtime.h>
#include <cuda_bf16.h>
#include <math.h>
#include <stdint.h>

// Problem constants
#define SEQ   2048
#define DM    1024
#define NH    16
#define DK    64
#define DFF   4096
#define NL    4
#define LN_EPS 1e-5f

// ---------------------------------------------------------------------------
// Scratch (static device globals: allocation-free kernel_launch)
// ---------------------------------------------------------------------------
__device__ float g_x[SEQ * DM];
__device__ float g_q[SEQ * DM];   // also reused as ctx
__device__ float g_k[SEQ * DM];
__device__ float g_v[SEQ * DM];
__device__ float g_t[SEQ * DM];   // attn_out / ffn_out
__device__ float g_h[SEQ * DFF];
__device__ float g_s[(size_t)NH * SEQ * SEQ];   // attention scores, 256 MB

// ---------------------------------------------------------------------------
// Small helpers
// ---------------------------------------------------------------------------
__device__ __forceinline__ uint32_t smem_u32(const void* p) {
    return (uint32_t)__cvta_generic_to_shared(p);
}
__device__ __forceinline__ uint32_t packbf(float a, float b) {
    __nv_bfloat162 t = __floats2bfloat162_rn(a, b);
    return *reinterpret_cast<uint32_t*>(&t);
}
__device__ __forceinline__ float lores(float a) {
    return a - __bfloat162float(__float2bfloat16_rn(a));
}

__device__ __forceinline__ void ldsm_x4(uint32_t* r, uint32_t addr) {
    asm volatile("ldmatrix.sync.aligned.m8n8.x4.shared.b16 {%0,%1,%2,%3}, [%4];\n"
                 : "=r"(r[0]), "=r"(r[1]), "=r"(r[2]), "=r"(r[3]) : "r"(addr));
}
__device__ __forceinline__ void ldsm_x4_t(uint32_t* r, uint32_t addr) {
    asm volatile("ldmatrix.sync.aligned.m8n8.x4.trans.shared.b16 {%0,%1,%2,%3}, [%4];\n"
                 : "=r"(r[0]), "=r"(r[1]), "=r"(r[2]), "=r"(r[3]) : "r"(addr));
}
__device__ __forceinline__ void mma_bf16(float* c, const uint32_t* a, const uint32_t* b) {
    asm volatile(
        "mma.sync.aligned.m16n8k16.row.col.f32.bf16.bf16.f32 "
        "{%0,%1,%2,%3}, {%4,%5,%6,%7}, {%8,%9}, {%0,%1,%2,%3};\n"
        : "+f"(c[0]), "+f"(c[1]), "+f"(c[2]), "+f"(c[3])
        : "r"(a[0]), "r"(a[1]), "r"(a[2]), "r"(a[3]), "r"(b[0]), "r"(b[1]));
}

// ---------------------------------------------------------------------------
// bf16x3 tensor-core GEMM (fp32-accurate):
//   C[z] = act( alpha * A[z] @ (B[z] or B[z]^T) + bias )
// A: [M,K] rm (lda); B: [K,N] rm (NN) or [N,K] rm (NT); C: [M,N] (ldc).
// fp32 inputs are split on-the-fly into bf16 hi/lo; 3 MMAs recover fp32-ish
// precision (err ~2^-17 per product, fp32 accumulate).
// Block tile: 128 x (NTT*32) x 32, 8 warps (2x4), warp tile 64 x (NTT*8).
// All dims assumed multiples of tile sizes (true at every call site).
// ---------------------------------------------------------------------------
template<int NTT, bool TRANSB, int ACT>
__global__ __launch_bounds__(256, 1)
void gemm3_k(const float* __restrict__ Ag, const float* __restrict__ Bg,
             const float* __restrict__ bias, float* __restrict__ Cg,
             int M, int N, int K, int lda, int ldb, int ldc,
             size_t sA, size_t sB, size_t sC, float alpha)
{
    constexpr int BM = 128, BK = 32;
    constexpr int BN = NTT * 32;          // 4 warp-cols * NTT * 8
    constexpr int AS = BK + 8;            // 40 bf16 row stride (odd 16B units)
    constexpr int BS = BN + 8;            // 136 / 72 bf16 row stride
    constexpr int BP = BN / 32;           // B tile float4 passes (4 or 2)

    __shared__ __nv_bfloat16 AsH[BM * AS], AsL[BM * AS];
    __shared__ __nv_bfloat16 BsH[BK * BS], BsL[BK * BS];

    const int tid  = threadIdx.x;
    const int lane = tid & 31;
    const int warp = tid >> 5;
    const int wm0  = (warp & 1) * 64;
    const int wn0  = (warp >> 1) * (NTT * 8);
    const int bm0  = blockIdx.y * BM;
    const int bn0  = blockIdx.x * BN;
    const float* A = Ag + (size_t)blockIdx.z * sA;
    const float* B = Bg + (size_t)blockIdx.z * sB;
    float*       C = Cg + (size_t)blockIdx.z * sC;

    float acc[4][NTT][4];
#pragma unroll
    for (int i = 0; i < 4; i++)
#pragma unroll
        for (int j = 0; j < NTT; j++)
#pragma unroll
            for (int q = 0; q < 4; q++) acc[i][j][q] = 0.f;

    float4 pa[4], pb[BP];

    // ---- global tile fetch into registers
    auto ldTiles = [&](int k0) {
#pragma unroll
        for (int p = 0; p < 4; p++) {
            int idx = p * 256 + tid;
            int r = idx >> 3, c4 = idx & 7;
            pa[p] = *(const float4*)&A[(size_t)(bm0 + r) * lda + k0 + c4 * 4];
        }
        if (!TRANSB) {
#pragma unroll
            for (int p = 0; p < BP; p++) {
                int idx = p * 256 + tid;
                int r = idx / (BN / 4), c4 = idx % (BN / 4);
                pb[p] = *(const float4*)&B[(size_t)(k0 + r) * ldb + bn0 + c4 * 4];
            }
        } else {
#pragma unroll
            for (int p = 0; p < BP; p++) {
                int idx = p * 256 + tid;
                int n = idx >> 3, k4 = idx & 7;
                pb[p] = *(const float4*)&B[(size_t)(bn0 + n) * ldb + k0 + k4 * 4];
            }
        }
    };

    // ---- convert to bf16 hi/lo and store into smem
    auto stTiles = [&]() {
#pragma unroll
        for (int p = 0; p < 4; p++) {
            int idx = p * 256 + tid;
            int r = idx >> 3, c4 = idx & 7;
            float4 v = pa[p];
            uint32_t* dH = (uint32_t*)&AsH[r * AS + c4 * 4];
            uint32_t* dL = (uint32_t*)&AsL[r * AS + c4 * 4];
            dH[0] = packbf(v.x, v.y);  dH[1] = packbf(v.z, v.w);
            dL[0] = packbf(lores(v.x), lores(v.y));
            dL[1] = packbf(lores(v.z), lores(v.w));
        }
        if (!TRANSB) {
#pragma unroll
            for (int p = 0; p < BP; p++) {
                int idx = p * 256 + tid;
                int r = idx / (BN / 4), c4 = idx % (BN / 4);
                float4 v = pb[p];
                uint32_t* dH = (uint32_t*)&BsH[r * BS + c4 * 4];
                uint32_t* dL = (uint32_t*)&BsL[r * BS + c4 * 4];
                dH[0] = packbf(v.x, v.y);  dH[1] = packbf(v.z, v.w);
                dL[0] = packbf(lores(v.x), lores(v.y));
                dL[1] = packbf(lores(v.z), lores(v.w));
            }
        } else {
#pragma unroll
            for (int p = 0; p < BP; p++) {
                int idx = p * 256 + tid;
                int n = idx >> 3, k4 = idx & 7;
                float4 v = pb[p];
                float vv[4] = {v.x, v.y, v.z, v.w};
#pragma unroll
                for (int j = 0; j < 4; j++) {
                    int kk = k4 * 4 + j;
                    BsH[kk * BS + n] = __float2bfloat16_rn(vv[j]);
                    BsL[kk * BS + n] = __float2bfloat16_rn(lores(vv[j]));
                }
            }
        }
    };

    // ---- one BK=32 tile worth of MMAs (two k16 chunks)
    auto compute = [&]() {
#pragma unroll
        for (int kc = 0; kc < 2; kc++) {
            const int kb = kc * 16;
            uint32_t aH[4][4], aL[4][4];
#pragma unroll
            for (int mt = 0; mt < 4; mt++) {
                int row = wm0 + mt * 16 + (lane & 15);
                int ko  = kb + ((lane >> 4) << 3);
                ldsm_x4(aH[mt], smem_u32(&AsH[row * AS + ko]));
                ldsm_x4(aL[mt], smem_u32(&AsL[row * AS + ko]));
            }
            uint32_t bH[NTT][2], bL[NTT][2];
#pragma unroll
            for (int np = 0; np < NTT / 2; np++) {
                int g  = lane >> 3;
                int rk = kb + (lane & 7) + ((g & 1) << 3);
                int nc = wn0 + np * 16 + ((g >> 1) << 3);
                uint32_t t4[4];
                ldsm_x4_t(t4, smem_u32(&BsH[rk * BS + nc]));
                bH[2*np][0] = t4[0]; bH[2*np][1] = t4[1];
                bH[2*np+1][0] = t4[2]; bH[2*np+1][1] = t4[3];
                ldsm_x4_t(t4, smem_u32(&BsL[rk * BS + nc]));
                bL[2*np][0] = t4[0]; bL[2*np][1] = t4[1];
                bL[2*np+1][0] = t4[2]; bL[2*np+1][1] = t4[3];
            }
#pragma unroll
            for (int mt = 0; mt < 4; mt++)
#pragma unroll
                for (int nt = 0; nt < NTT; nt++) {
                    mma_bf16(acc[mt][nt], aH[mt], bH[nt]);
                    mma_bf16(acc[mt][nt], aL[mt], bH[nt]);
                    mma_bf16(acc[mt][nt], aH[mt], bL[nt]);
                }
        }
    };

    // ---- main loop: register-staged single-buffer pipeline
    ldTiles(0);
    stTiles();
    __syncthreads();
    for (int k0 = BK; k0 < K; k0 += BK) {
        ldTiles(k0);
        compute();
        __syncthreads();
        stTiles();
        __syncthreads();
    }
    compute();

    // ---- epilogue
#pragma unroll
    for (int mt = 0; mt < 4; mt++) {
        int r0 = bm0 + wm0 + mt * 16 + (lane >> 2);
#pragma unroll
        for (int nt = 0; nt < NTT; nt++) {
            int c = bn0 + wn0 + nt * 8 + (lane & 3) * 2;
            float b0 = 0.f, b1 = 0.f;
            if (bias != nullptr) { b0 = bias[c]; b1 = bias[c + 1]; }
            float v[4];
#pragma unroll
            for (int q = 0; q < 4; q++) {
                float x = acc[mt][nt][q] * alpha + ((q & 1) ? b1 : b0);
                if (ACT == 1) {
                    float tt = tanhf(0.7978845608028654f * (x + 0.044715f * x * x * x));
                    x = 0.5f * x * (1.f + tt);
                }
                v[q] = x;
            }
            *(float2*)&C[(size_t)r0 * ldc + c]       = make_float2(v[0], v[1]);
            *(float2*)&C[(size_t)(r0 + 8) * ldc + c] = make_float2(v[2], v[3]);
        }
    }
}

// ---------------------------------------------------------------------------
// Softmax over rows of length 2048 (register-resident, 1 read + 1 write)
// ---------------------------------------------------------------------------
__global__ __launch_bounds__(256)
void softmax2048_k(float* __restrict__ data)
{
    const int tid = threadIdx.x;
    float4* p4 = (float4*)(data + (size_t)blockIdx.x * 2048);
    float4 a = p4[tid];
    float4 b = p4[tid + 256];

    __shared__ float red[256];

    float m = fmaxf(fmaxf(fmaxf(a.x, a.y), fmaxf(a.z, a.w)),
                    fmaxf(fmaxf(b.x, b.y), fmaxf(b.z, b.w)));
    red[tid] = m; __syncthreads();
#pragma unroll
    for (int s = 128; s > 0; s >>= 1) {
        if (tid < s) red[tid] = fmaxf(red[tid], red[tid + s]);
        __syncthreads();
    }
    m = red[0];
    __syncthreads();

    a.x = __expf(a.x - m); a.y = __expf(a.y - m);
    a.z = __expf(a.z - m); a.w = __expf(a.w - m);
    b.x = __expf(b.x - m); b.y = __expf(b.y - m);
    b.z = __expf(b.z - m); b.w = __expf(b.w - m);

    float sum = a.x + a.y + a.z + a.w + b.x + b.y + b.z + b.w;
    red[tid] = sum; __syncthreads();
#pragma unroll
    for (int s = 128; s > 0; s >>= 1) {
        if (tid < s) red[tid] += red[tid + s];
        __syncthreads();
    }
    float inv = 1.0f / red[0];

    a.x *= inv; a.y *= inv; a.z *= inv; a.w *= inv;
    b.x *= inv; b.y *= inv; b.z *= inv; b.w *= inv;
    p4[tid] = a;
    p4[tid + 256] = b;
}

// ---------------------------------------------------------------------------
// Fused residual + LayerNorm over rows of 1024: out = LN(x + sub) * g + b
// ---------------------------------------------------------------------------
__global__ __launch_bounds__(256)
void ln_k(const float* __restrict__ x, const float* __restrict__ sub,
          const float* __restrict__ g, const float* __restrict__ b,
          float* __restrict__ out)
{
    const int tid = threadIdx.x;
    const size_t base = (size_t)blockIdx.x * DM + tid * 4;

    float4 xv = *(const float4*)(x + base);
    float4 sv = *(const float4*)(sub + base);
    float v0 = xv.x + sv.x, v1 = xv.y + sv.y, v2 = xv.z + sv.z, v3 = xv.w + sv.w;

    __shared__ float red[256];
    red[tid] = v0 + v1 + v2 + v3; __syncthreads();
#pragma unroll
    for (int s = 128; s > 0; s >>= 1) {
        if (tid < s) red[tid] += red[tid + s];
        __syncthreads();
    }
    const float mu = red[0] * (1.f / DM);
    __syncthreads();

    const float d0 = v0 - mu, d1 = v1 - mu, d2 = v2 - mu, d3 = v3 - mu;
    red[tid] = d0 * d0 + d1 * d1 + d2 * d2 + d3 * d3; __syncthreads();
#pragma unroll
    for (int s = 128; s > 0; s >>= 1) {
        if (tid < s) red[tid] += red[tid + s];
        __syncthreads();
    }
    const float inv = rsqrtf(red[0] * (1.f / DM) + LN_EPS);

    float4 gv = *(const float4*)(g + tid * 4);
    float4 bv = *(const float4*)(b + tid * 4);
    float4 o;
    o.x = d0 * inv * gv.x + bv.x;
    o.y = d1 * inv * gv.y + bv.y;
    o.z = d2 * inv * gv.z + bv.z;
    o.w = d3 * inv * gv.w + bv.w;
    *(float4*)(out + base) = o;
}

// ---------------------------------------------------------------------------
// Host launcher
// ---------------------------------------------------------------------------
extern "C" void kernel_launch(void* const* d_in, const int* in_sizes, int n_in,
                              void* d_out, int out_size)
{
    (void)in_sizes; (void)n_in; (void)out_size;

    const float* x_in = (const float*)d_in[0];
    const float* wq  = (const float*)d_in[1];
    const float* bq  = (const float*)d_in[2];
    const float* wk  = (const float*)d_in[3];
    const float* bk  = (const float*)d_in[4];
    const float* wv  = (const float*)d_in[5];
    const float* bv  = (const float*)d_in[6];
    const float* wo  = (const float*)d_in[7];
    const float* bo  = (const float*)d_in[8];
    const float* w1  = (const float*)d_in[9];
    const float* b1  = (const float*)d_in[10];
    const float* w2  = (const float*)d_in[11];
    const float* b2  = (const float*)d_in[12];
    const float* ln1g = (const float*)d_in[13];
    const float* ln1b = (const float*)d_in[14];
    const float* ln2g = (const float*)d_in[15];
    const float* ln2b = (const float*)d_in[16];

    float *x, *q, *k, *v, *t, *h, *s;
    cudaGetSymbolAddress((void**)&x, g_x);
    cudaGetSymbolAddress((void**)&q, g_q);
    cudaGetSymbolAddress((void**)&k, g_k);
    cudaGetSymbolAddress((void**)&v, g_v);
    cudaGetSymbolAddress((void**)&t, g_t);
    cudaGetSymbolAddress((void**)&h, g_h);
    cudaGetSymbolAddress((void**)&s, g_s);

    cudaMemcpyAsync(x, x_in, (size_t)SEQ * DM * sizeof(float),
                    cudaMemcpyDeviceToDevice, 0);

    for (int l = 0; l < NL; l++) {
        const float* Wq = wq + (size_t)l * DM * DM;
        const float* Wk = wk + (size_t)l * DM * DM;
        const float* Wv = wv + (size_t)l * DM * DM;
        const float* Wo = wo + (size_t)l * DM * DM;
        const float* W1 = w1 + (size_t)l * DM * DFF;
        const float* W2 = w2 + (size_t)l * DFF * DM;
        const float* Bq = bq + (size_t)l * DM;
        const float* Bk = bk + (size_t)l * DM;
        const float* Bv = bv + (size_t)l * DM;
        const float* Bo = bo + (size_t)l * DM;
        const float* B1 = b1 + (size_t)l * DFF;
        const float* B2 = b2 + (size_t)l * DM;
        const float* G1 = ln1g + (size_t)l * DM;
        const float* Be1 = ln1b + (size_t)l * DM;
        const float* G2 = ln2g + (size_t)l * DM;
        const float* Be2 = ln2b + (size_t)l * DM;

        dim3 gProj(DM / 128, SEQ / 128, 1);
        // Q, K, V projections
        gemm3_k<4,false,0><<<gProj,256>>>(x, Wq, Bq, q, SEQ, DM, DM,
                                          DM, DM, DM, 0, 0, 0, 1.f);
        gemm3_k<4,false,0><<<gProj,256>>>(x, Wk, Bk, k, SEQ, DM, DM,
                                          DM, DM, DM, 0, 0, 0, 1.f);
        gemm3_k<4,false,0><<<gProj,256>>>(x, Wv, Bv, v, SEQ, DM, DM,
                                          DM, DM, DM, 0, 0, 0, 1.f);
        // scores[h] = (Q_h @ K_h^T) / 8   (batched NT over heads)
        gemm3_k<4,true,0><<<dim3(SEQ/128, SEQ/128, NH),256>>>(
            q, k, nullptr, s, SEQ, SEQ, DK,
            DM, DM, SEQ,
            (size_t)DK, (size_t)DK, (size_t)SEQ * SEQ, 0.125f);
        // softmax over last dim
        softmax2048_k<<<NH * SEQ, 256>>>(s);
        // ctx[h] = attn[h] @ V_h   (batched NN, N=64) -> reuse q buffer
        gemm3_k<2,false,0><<<dim3(1, SEQ/128, NH),256>>>(
            s, v, nullptr, q, SEQ, DK, SEQ,
            SEQ, DM, DM,
            (size_t)SEQ * SEQ, (size_t)DK, (size_t)DK, 1.f);
        // attn_out = ctx @ Wo + bo
        gemm3_k<4,false,0><<<gProj,256>>>(q, Wo, Bo, t, SEQ, DM, DM,
                                          DM, DM, DM, 0, 0, 0, 1.f);
        // x = LN1(x + attn_out)
        ln_k<<<SEQ,256>>>(x, t, G1, Be1, x);
        // h = gelu(x @ W1 + b1)
        gemm3_k<4,false,1><<<dim3(DFF/128, SEQ/128, 1),256>>>(
            x, W1, B1, h, SEQ, DFF, DM,
            DM, DFF, DFF, 0, 0, 0, 1.f);
        // ffn_out = h @ W2 + b2
        gemm3_k<4,false,0><<<dim3(DM/128, SEQ/128, 1),256>>>(
            h, W2, B2, t, SEQ, DM, DFF,
            DFF, DM, DM, 0, 0, 0, 1.f);
        // x = LN2(x + ffn_out); final layer writes straight to d_out
        float* outp = (l == NL - 1) ? (float*)d_out : x;
        ln_k<<<SEQ,256>>>(x, t, G2, Be2, outp);
    }
}

// round 4
// speedup vs baseline: 3.5779x; 1.1362x over previous
#include <cuda_runtime.h>
#include <cuda_bf16.h>
#include <math.h>
#include <stdint.h>

// Problem constants
#define SEQ   2048
#define DM    1024
#define NH    16
#define DK    64
#define DFF   4096
#define NL    4
#define LN_EPS 1e-5f

// ---------------------------------------------------------------------------
// Scratch (static device globals: allocation-free kernel_launch)
// ---------------------------------------------------------------------------
__device__ __nv_bfloat16 g_wqh[NL*DM*DM],  g_wql[NL*DM*DM];
__device__ __nv_bfloat16 g_wkh[NL*DM*DM],  g_wkl[NL*DM*DM];
__device__ __nv_bfloat16 g_wvh[NL*DM*DM],  g_wvl[NL*DM*DM];
__device__ __nv_bfloat16 g_woh[NL*DM*DM],  g_wol[NL*DM*DM];
__device__ __nv_bfloat16 g_w1h[NL*DM*DFF], g_w1l[NL*DM*DFF];
__device__ __nv_bfloat16 g_w2h[NL*DFF*DM], g_w2l[NL*DFF*DM];
__device__ float g_x[SEQ*DM];
__device__ float g_t[SEQ*DM];
__device__ __nv_bfloat16 g_xh[SEQ*DM], g_xl[SEQ*DM];
__device__ __nv_bfloat16 g_qh[SEQ*DM], g_ql[SEQ*DM];
__device__ __nv_bfloat16 g_kh[SEQ*DM], g_kl[SEQ*DM];
__device__ __nv_bfloat16 g_vh[SEQ*DM], g_vl[SEQ*DM];
__device__ __nv_bfloat16 g_ch[SEQ*DM], g_cl[SEQ*DM];
__device__ __nv_bfloat16 g_hh[SEQ*DFF], g_hl[SEQ*DFF];

// ---------------------------------------------------------------------------
// Helpers
// ---------------------------------------------------------------------------
__device__ __forceinline__ uint32_t smem_u32(const void* p) {
    return (uint32_t)__cvta_generic_to_shared(p);
}
__device__ __forceinline__ uint32_t packbf(float a, float b) {
    __nv_bfloat162 t = __floats2bfloat162_rn(a, b);
    return *reinterpret_cast<uint32_t*>(&t);
}
__device__ __forceinline__ float lores(float a) {
    return a - __bfloat162float(__float2bfloat16_rn(a));
}
__device__ __forceinline__ void cp16(uint32_t dst, const void* src) {
    asm volatile("cp.async.cg.shared.global [%0], [%1], 16;\n" :: "r"(dst), "l"(src));
}
__device__ __forceinline__ void cp_commit() {
    asm volatile("cp.async.commit_group;\n" ::);
}
template<int N>
__device__ __forceinline__ void cp_wait() {
    asm volatile("cp.async.wait_group %0;\n" :: "n"(N));
}
__device__ __forceinline__ void ldsm_x4(uint32_t* r, uint32_t addr) {
    asm volatile("ldmatrix.sync.aligned.m8n8.x4.shared.b16 {%0,%1,%2,%3}, [%4];\n"
                 : "=r"(r[0]), "=r"(r[1]), "=r"(r[2]), "=r"(r[3]) : "r"(addr));
}
__device__ __forceinline__ void ldsm_x4_t(uint32_t* r, uint32_t addr) {
    asm volatile("ldmatrix.sync.aligned.m8n8.x4.trans.shared.b16 {%0,%1,%2,%3}, [%4];\n"
                 : "=r"(r[0]), "=r"(r[1]), "=r"(r[2]), "=r"(r[3]) : "r"(addr));
}
__device__ __forceinline__ void mma_bf16(float* c, const uint32_t* a, const uint32_t* b) {
    asm volatile(
        "mma.sync.aligned.m16n8k16.row.col.f32.bf16.bf16.f32 "
        "{%0,%1,%2,%3}, {%4,%5,%6,%7}, {%8,%9}, {%0,%1,%2,%3};\n"
        : "+f"(c[0]), "+f"(c[1]), "+f"(c[2]), "+f"(c[3])
        : "r"(a[0]), "r"(a[1]), "r"(a[2]), "r"(a[3]), "r"(b[0]), "r"(b[1]));
}

// ---------------------------------------------------------------------------
// fp32 -> (bf16 hi, bf16 lo) elementwise split, float4-wide
// ---------------------------------------------------------------------------
__global__ __launch_bounds__(256)
void split_k(const float* __restrict__ s, __nv_bfloat16* __restrict__ hi,
             __nv_bfloat16* __restrict__ lo, int n4)
{
    int i = blockIdx.x * 256 + threadIdx.x;
    if (i >= n4) return;
    float4 v = ((const float4*)s)[i];
    uint32_t* H = (uint32_t*)hi;
    uint32_t* L = (uint32_t*)lo;
    H[i*2]   = packbf(v.x, v.y);
    H[i*2+1] = packbf(v.z, v.w);
    L[i*2]   = packbf(lores(v.x), lores(v.y));
    L[i*2+1] = packbf(lores(v.z), lores(v.w));
}

// ---------------------------------------------------------------------------
// Pipelined bf16x3 tensor-core GEMM on pre-split inputs:
//   C = act( A @ B + bias ),  A: [M,K] hi/lo bf16 rm, B: [K,N] hi/lo bf16 rm.
// Outputs (each optional): Cf fp32, (Ch,Cl) bf16 hi/lo split of the result.
// Tile 128x128x32, 8 warps (2x4), warp tile 64x32. 3-stage cp.async pipeline.
// Dims must be multiples of 128/128/32 (true at all call sites).
// smem strides: A rows 32+8=40 elems (80B), B rows 128+8=136 elems (272B).
// ---------------------------------------------------------------------------
#define GSM_STAGE 37888
#define GSM_TOTAL (3 * GSM_STAGE)

template<int ACT>
__global__ __launch_bounds__(256, 1)
void gemm_s(const __nv_bfloat16* __restrict__ Ahg, const __nv_bfloat16* __restrict__ Alg,
            const __nv_bfloat16* __restrict__ Bhg, const __nv_bfloat16* __restrict__ Blg,
            const float* __restrict__ bias,
            float* __restrict__ Cf, __nv_bfloat16* __restrict__ Ch,
            __nv_bfloat16* __restrict__ Cl, int N, int K)
{
    extern __shared__ char smem[];
    const int tid = threadIdx.x, lane = tid & 31, warp = tid >> 5;
    const int wm0 = (warp & 1) * 64, wn0 = (warp >> 1) * 32;
    const int bm0 = blockIdx.y * 128, bn0 = blockIdx.x * 128;

    auto Ah_s = [&](int s){ return (__nv_bfloat16*)(smem + s*GSM_STAGE); };
    auto Al_s = [&](int s){ return (__nv_bfloat16*)(smem + s*GSM_STAGE + 10240); };
    auto Bh_s = [&](int s){ return (__nv_bfloat16*)(smem + s*GSM_STAGE + 20480); };
    auto Bl_s = [&](int s){ return (__nv_bfloat16*)(smem + s*GSM_STAGE + 29184); };

    auto load_stage = [&](int s, int kt) {
        const int k0 = kt * 32;
        __nv_bfloat16 *ah = Ah_s(s), *al = Al_s(s), *bh = Bh_s(s), *bl = Bl_s(s);
#pragma unroll
        for (int p = 0; p < 2; p++) {
            int c = p * 256 + tid;
            int r = c >> 2, sg = c & 3;
            size_t go = (size_t)(bm0 + r) * K + k0 + sg * 8;
            cp16(smem_u32(ah + r*40 + sg*8), Ahg + go);
            cp16(smem_u32(al + r*40 + sg*8), Alg + go);
        }
#pragma unroll
        for (int p = 0; p < 2; p++) {
            int c = p * 256 + tid;
            int r = c >> 4, sg = c & 15;
            size_t go = (size_t)(k0 + r) * N + bn0 + sg * 8;
            cp16(smem_u32(bh + r*136 + sg*8), Bhg + go);
            cp16(smem_u32(bl + r*136 + sg*8), Blg + go);
        }
    };

    float acc[4][4][4];
#pragma unroll
    for (int i = 0; i < 4; i++)
#pragma unroll
        for (int j = 0; j < 4; j++)
#pragma unroll
            for (int q = 0; q < 4; q++) acc[i][j][q] = 0.f;

    const int KT = K / 32;
    load_stage(0, 0); cp_commit();
    load_stage(1, 1); cp_commit();

    for (int kt = 0; kt < KT; kt++) {
        if (kt + 2 < KT) load_stage((kt + 2) % 3, kt + 2);
        cp_commit();
        cp_wait<2>();
        __syncthreads();

        const int s = kt % 3;
        const __nv_bfloat16 *ah = Ah_s(s), *al = Al_s(s), *bh = Bh_s(s), *bl = Bl_s(s);
#pragma unroll
        for (int kc = 0; kc < 2; kc++) {
            const int kb = kc * 16;
            uint32_t aH[4][4], aL[4][4];
#pragma unroll
            for (int mt = 0; mt < 4; mt++) {
                int row = wm0 + mt * 16 + (lane & 15);
                int ko  = kb + ((lane >> 4) << 3);
                ldsm_x4(aH[mt], smem_u32(ah + row*40 + ko));
                ldsm_x4(aL[mt], smem_u32(al + row*40 + ko));
            }
            uint32_t bH[4][2], bL[4][2];
#pragma unroll
            for (int np = 0; np < 2; np++) {
                int g  = lane >> 3;
                int rk = kb + (lane & 7) + ((g & 1) << 3);
                int nc = wn0 + np * 16 + ((g >> 1) << 3);
                uint32_t t4[4];
                ldsm_x4_t(t4, smem_u32(bh + rk*136 + nc));
                bH[2*np][0] = t4[0]; bH[2*np][1] = t4[1];
                bH[2*np+1][0] = t4[2]; bH[2*np+1][1] = t4[3];
                ldsm_x4_t(t4, smem_u32(bl + rk*136 + nc));
                bL[2*np][0] = t4[0]; bL[2*np][1] = t4[1];
                bL[2*np+1][0] = t4[2]; bL[2*np+1][1] = t4[3];
            }
#pragma unroll
            for (int mt = 0; mt < 4; mt++)
#pragma unroll
                for (int nt = 0; nt < 4; nt++) {
                    mma_bf16(acc[mt][nt], aH[mt], bH[nt]);
                    mma_bf16(acc[mt][nt], aL[mt], bH[nt]);
                    mma_bf16(acc[mt][nt], aH[mt], bL[nt]);
                }
        }
        __syncthreads();
    }

    // epilogue
#pragma unroll
    for (int mt = 0; mt < 4; mt++) {
        int r0 = bm0 + wm0 + mt * 16 + (lane >> 2);
#pragma unroll
        for (int nt = 0; nt < 4; nt++) {
            int c = bn0 + wn0 + nt * 8 + (lane & 3) * 2;
            float b0 = bias[c], b1 = bias[c + 1];
            float v[4];
#pragma unroll
            for (int q = 0; q < 4; q++) {
                float x = acc[mt][nt][q] + ((q & 1) ? b1 : b0);
                if (ACT == 1) {
                    float tt = tanhf(0.7978845608028654f * (x + 0.044715f * x * x * x));
                    x = 0.5f * x * (1.f + tt);
                }
                v[q] = x;
            }
            size_t o0 = (size_t)r0 * N + c, o1 = (size_t)(r0 + 8) * N + c;
            if (Cf) {
                *(float2*)&Cf[o0] = make_float2(v[0], v[1]);
                *(float2*)&Cf[o1] = make_float2(v[2], v[3]);
            }
            if (Ch) {
                ((uint32_t*)Ch)[o0 >> 1] = packbf(v[0], v[1]);
                ((uint32_t*)Ch)[o1 >> 1] = packbf(v[2], v[3]);
                ((uint32_t*)Cl)[o0 >> 1] = packbf(lores(v[0]), lores(v[1]));
                ((uint32_t*)Cl)[o1 >> 1] = packbf(lores(v[2]), lores(v[3]));
            }
        }
    }
}

// ---------------------------------------------------------------------------
// Flash attention: per block = (q-block of 128 rows, head).
// S = (Q_h K_h^T)/8 via bf16x3; online softmax; O += P V via bf16x3.
// 8 warps, each owns 16 q-rows (full 128-key tile width -> warp-local softmax).
// K/V tiles (128x64) double-buffered via cp.async. Output: ctx hi/lo bf16.
// smem tile stride: 64+8=72 elems (144B).
// ---------------------------------------------------------------------------
#define FSM_ARR   18432                    // 128*72*2 bytes
#define FSM_KV0   (2 * FSM_ARR)            // after Qh,Ql
#define FSM_STAGE (4 * FSM_ARR)            // Kh,Kl,Vh,Vl
#define FSM_TOTAL (FSM_KV0 + 2 * FSM_STAGE)

__global__ __launch_bounds__(256, 1)
void flash_k(const __nv_bfloat16* __restrict__ Qh, const __nv_bfloat16* __restrict__ Ql,
             const __nv_bfloat16* __restrict__ Kh, const __nv_bfloat16* __restrict__ Kl,
             const __nv_bfloat16* __restrict__ Vh, const __nv_bfloat16* __restrict__ Vl,
             __nv_bfloat16* __restrict__ Ch, __nv_bfloat16* __restrict__ Cl)
{
    extern __shared__ char smem[];
    const int tid = threadIdx.x, lane = tid & 31, warp = tid >> 5;
    const int qb = blockIdx.x, head = blockIdx.y;
    const int col0 = head * DK;

    __nv_bfloat16* Qsh = (__nv_bfloat16*)smem;
    __nv_bfloat16* Qsl = (__nv_bfloat16*)(smem + FSM_ARR);
    auto Ksh = [&](int s){ return (__nv_bfloat16*)(smem + FSM_KV0 + s*FSM_STAGE); };
    auto Ksl = [&](int s){ return (__nv_bfloat16*)(smem + FSM_KV0 + s*FSM_STAGE + FSM_ARR); };
    auto Vsh = [&](int s){ return (__nv_bfloat16*)(smem + FSM_KV0 + s*FSM_STAGE + 2*FSM_ARR); };
    auto Vsl = [&](int s){ return (__nv_bfloat16*)(smem + FSM_KV0 + s*FSM_STAGE + 3*FSM_ARR); };

    // load Q tile once
#pragma unroll
    for (int p = 0; p < 4; p++) {
        int c = p * 256 + tid;
        int r = c >> 3, sg = c & 7;
        size_t go = (size_t)(qb * 128 + r) * DM + col0 + sg * 8;
        cp16(smem_u32(Qsh + r*72 + sg*8), Qh + go);
        cp16(smem_u32(Qsl + r*72 + sg*8), Ql + go);
    }
    auto load_kv = [&](int s, int t) {
#pragma unroll
        for (int p = 0; p < 4; p++) {
            int c = p * 256 + tid;
            int r = c >> 3, sg = c & 7;
            size_t go = (size_t)(t * 128 + r) * DM + col0 + sg * 8;
            cp16(smem_u32(Ksh(s) + r*72 + sg*8), Kh + go);
            cp16(smem_u32(Ksl(s) + r*72 + sg*8), Kl + go);
            cp16(smem_u32(Vsh(s) + r*72 + sg*8), Vh + go);
            cp16(smem_u32(Vsl(s) + r*72 + sg*8), Vl + go);
        }
    };
    load_kv(0, 0);
    cp_commit();

    float oacc[8][4];
#pragma unroll
    for (int i = 0; i < 8; i++)
#pragma unroll
        for (int q = 0; q < 4; q++) oacc[i][q] = 0.f;
    float mrun[2] = {-INFINITY, -INFINITY};
    float lrun[2] = {0.f, 0.f};

    const int NT_KV = SEQ / 128;
    for (int t = 0; t < NT_KV; t++) {
        if (t + 1 < NT_KV) load_kv((t + 1) & 1, t + 1);
        cp_commit();
        cp_wait<1>();
        __syncthreads();

        const int s = t & 1;
        const __nv_bfloat16 *ksh = Ksh(s), *ksl = Ksl(s), *vsh = Vsh(s), *vsl = Vsl(s);

        // ---- S = Q K^T (bf16x3)
        float sacc[16][4];
#pragma unroll
        for (int i = 0; i < 16; i++)
#pragma unroll
            for (int q = 0; q < 4; q++) sacc[i][q] = 0.f;

#pragma unroll
        for (int kc = 0; kc < 4; kc++) {
            const int kb = kc * 16;
            uint32_t aH[4], aL[4];
            {
                int row = warp * 16 + (lane & 15);
                int ko  = kb + ((lane >> 4) << 3);
                ldsm_x4(aH, smem_u32(Qsh + row*72 + ko));
                ldsm_x4(aL, smem_u32(Qsl + row*72 + ko));
            }
#pragma unroll
            for (int np = 0; np < 8; np++) {
                // non-trans B mapping on [key][d] layout: n=key, k=d
                int nrow = np * 16 + (lane & 7) + ((lane >> 4) << 3);
                int kbase = kb + (((lane >> 3) & 1) << 3);
                uint32_t bh4[4], bl4[4];
                ldsm_x4(bh4, smem_u32(ksh + nrow*72 + kbase));
                ldsm_x4(bl4, smem_u32(ksl + nrow*72 + kbase));
                mma_bf16(sacc[2*np],   aH, bh4);
                mma_bf16(sacc[2*np],   aL, bh4);
                mma_bf16(sacc[2*np],   aH, bl4);
                mma_bf16(sacc[2*np+1], aH, bh4 + 2);
                mma_bf16(sacc[2*np+1], aL, bh4 + 2);
                mma_bf16(sacc[2*np+1], aH, bl4 + 2);
            }
        }

        // ---- online softmax (rows r=lane>>2 and r+8; cols spread over quad)
        float mnew[2];
#pragma unroll
        for (int rr = 0; rr < 2; rr++) {
            float m = -INFINITY;
#pragma unroll
            for (int nt = 0; nt < 16; nt++) {
                sacc[nt][2*rr]   *= 0.125f;
                sacc[nt][2*rr+1] *= 0.125f;
                m = fmaxf(m, fmaxf(sacc[nt][2*rr], sacc[nt][2*rr+1]));
            }
            m = fmaxf(m, __shfl_xor_sync(0xffffffffu, m, 1));
            m = fmaxf(m, __shfl_xor_sync(0xffffffffu, m, 2));
            mnew[rr] = fmaxf(mrun[rr], m);
        }
        float sc0 = __expf(mrun[0] - mnew[0]);
        float sc1 = __expf(mrun[1] - mnew[1]);
        float ls0 = 0.f, ls1 = 0.f;
#pragma unroll
        for (int nt = 0; nt < 16; nt++) {
            float p0 = __expf(sacc[nt][0] - mnew[0]);
            float p1 = __expf(sacc[nt][1] - mnew[0]);
            float p2 = __expf(sacc[nt][2] - mnew[1]);
            float p3 = __expf(sacc[nt][3] - mnew[1]);
            sacc[nt][0] = p0; sacc[nt][1] = p1; sacc[nt][2] = p2; sacc[nt][3] = p3;
            ls0 += p0 + p1; ls1 += p2 + p3;
        }
        ls0 += __shfl_xor_sync(0xffffffffu, ls0, 1);
        ls0 += __shfl_xor_sync(0xffffffffu, ls0, 2);
        ls1 += __shfl_xor_sync(0xffffffffu, ls1, 1);
        ls1 += __shfl_xor_sync(0xffffffffu, ls1, 2);
        lrun[0] = lrun[0] * sc0 + ls0;
        lrun[1] = lrun[1] * sc1 + ls1;
        mrun[0] = mnew[0]; mrun[1] = mnew[1];
#pragma unroll
        for (int nt = 0; nt < 8; nt++) {
            oacc[nt][0] *= sc0; oacc[nt][1] *= sc0;
            oacc[nt][2] *= sc1; oacc[nt][3] *= sc1;
        }

        // ---- O += P V (bf16x3): P frags built directly from registers
#pragma unroll
        for (int kt = 0; kt < 8; kt++) {
            uint32_t pH[4], pL[4];
            pH[0] = packbf(sacc[2*kt][0],   sacc[2*kt][1]);
            pH[1] = packbf(sacc[2*kt][2],   sacc[2*kt][3]);
            pH[2] = packbf(sacc[2*kt+1][0], sacc[2*kt+1][1]);
            pH[3] = packbf(sacc[2*kt+1][2], sacc[2*kt+1][3]);
            pL[0] = packbf(lores(sacc[2*kt][0]),   lores(sacc[2*kt][1]));
            pL[1] = packbf(lores(sacc[2*kt][2]),   lores(sacc[2*kt][3]));
            pL[2] = packbf(lores(sacc[2*kt+1][0]), lores(sacc[2*kt+1][1]));
            pL[3] = packbf(lores(sacc[2*kt+1][2]), lores(sacc[2*kt+1][3]));
#pragma unroll
            for (int np = 0; np < 4; np++) {
                int g  = lane >> 3;
                int rk = kt * 16 + (lane & 7) + ((g & 1) << 3);
                int nc = np * 16 + ((g >> 1) << 3);
                uint32_t bh4[4], bl4[4];
                ldsm_x4_t(bh4, smem_u32(vsh + rk*72 + nc));
                ldsm_x4_t(bl4, smem_u32(vsl + rk*72 + nc));
                mma_bf16(oacc[2*np],   pH, bh4);
                mma_bf16(oacc[2*np],   pL, bh4);
                mma_bf16(oacc[2*np],   pH, bl4);
                mma_bf16(oacc[2*np+1], pH, bh4 + 2);
                mma_bf16(oacc[2*np+1], pL, bh4 + 2);
                mma_bf16(oacc[2*np+1], pH, bl4 + 2);
            }
        }
        __syncthreads();
    }

    // ---- epilogue: ctx = O / l, write hi/lo split
    float inv0 = 1.f / lrun[0], inv1 = 1.f / lrun[1];
    int r0 = qb * 128 + warp * 16 + (lane >> 2);
#pragma unroll
    for (int nt = 0; nt < 8; nt++) {
        int c = col0 + nt * 8 + (lane & 3) * 2;
        float v0 = oacc[nt][0] * inv0, v1 = oacc[nt][1] * inv0;
        float v2 = oacc[nt][2] * inv1, v3 = oacc[nt][3] * inv1;
        size_t o0 = (size_t)r0 * DM + c, o1 = (size_t)(r0 + 8) * DM + c;
        ((uint32_t*)Ch)[o0 >> 1] = packbf(v0, v1);
        ((uint32_t*)Ch)[o1 >> 1] = packbf(v2, v3);
        ((uint32_t*)Cl)[o0 >> 1] = packbf(lores(v0), lores(v1));
        ((uint32_t*)Cl)[o1 >> 1] = packbf(lores(v2), lores(v3));
    }
}

// ---------------------------------------------------------------------------
// Fused residual + LayerNorm (1024): out = LN(x+sub)*g + b, plus hi/lo split
// ---------------------------------------------------------------------------
__global__ __launch_bounds__(256)
void ln_k(const float* __restrict__ x, const float* __restrict__ sub,
          const float* __restrict__ g, const float* __restrict__ b,
          float* __restrict__ out, __nv_bfloat16* __restrict__ oh,
          __nv_bfloat16* __restrict__ ol)
{
    const int tid = threadIdx.x;
    const size_t base = (size_t)blockIdx.x * DM + tid * 4;

    float4 xv = *(const float4*)(x + base);
    float4 sv = *(const float4*)(sub + base);
    float v0 = xv.x + sv.x, v1 = xv.y + sv.y, v2 = xv.z + sv.z, v3 = xv.w + sv.w;

    __shared__ float red[256];
    red[tid] = v0 + v1 + v2 + v3; __syncthreads();
#pragma unroll
    for (int s = 128; s > 0; s >>= 1) {
        if (tid < s) red[tid] += red[tid + s];
        __syncthreads();
    }
    const float mu = red[0] * (1.f / DM);
    __syncthreads();

    const float d0 = v0 - mu, d1 = v1 - mu, d2 = v2 - mu, d3 = v3 - mu;
    red[tid] = d0*d0 + d1*d1 + d2*d2 + d3*d3; __syncthreads();
#pragma unroll
    for (int s = 128; s > 0; s >>= 1) {
        if (tid < s) red[tid] += red[tid + s];
        __syncthreads();
    }
    const float inv = rsqrtf(red[0] * (1.f / DM) + LN_EPS);

    float4 gv = *(const float4*)(g + tid * 4);
    float4 bv = *(const float4*)(b + tid * 4);
    float o0 = d0 * inv * gv.x + bv.x;
    float o1 = d1 * inv * gv.y + bv.y;
    float o2 = d2 * inv * gv.z + bv.z;
    float o3 = d3 * inv * gv.w + bv.w;
    *(float4*)(out + base) = make_float4(o0, o1, o2, o3);
    if (oh) {
        ((uint32_t*)oh)[base >> 1]       = packbf(o0, o1);
        ((uint32_t*)oh)[(base >> 1) + 1] = packbf(o2, o3);
        ((uint32_t*)ol)[base >> 1]       = packbf(lores(o0), lores(o1));
        ((uint32_t*)ol)[(base >> 1) + 1] = packbf(lores(o2), lores(o3));
    }
}

// ---------------------------------------------------------------------------
// Host launcher
// ---------------------------------------------------------------------------
extern "C" void kernel_launch(void* const* d_in, const int* in_sizes, int n_in,
                              void* d_out, int out_size)
{
    (void)in_sizes; (void)n_in; (void)out_size;

    const float* x_in = (const float*)d_in[0];
    const float* wq  = (const float*)d_in[1];
    const float* bq  = (const float*)d_in[2];
    const float* wk  = (const float*)d_in[3];
    const float* bk  = (const float*)d_in[4];
    const float* wv  = (const float*)d_in[5];
    const float* bv  = (const float*)d_in[6];
    const float* wo  = (const float*)d_in[7];
    const float* bo  = (const float*)d_in[8];
    const float* w1  = (const float*)d_in[9];
    const float* b1  = (const float*)d_in[10];
    const float* w2  = (const float*)d_in[11];
    const float* b2  = (const float*)d_in[12];
    const float* ln1g = (const float*)d_in[13];
    const float* ln1b = (const float*)d_in[14];
    const float* ln2g = (const float*)d_in[15];
    const float* ln2b = (const float*)d_in[16];

    static bool attr_done = false;
    if (!attr_done) {
        cudaFuncSetAttribute(gemm_s<0>, cudaFuncAttributeMaxDynamicSharedMemorySize, GSM_TOTAL);
        cudaFuncSetAttribute(gemm_s<1>, cudaFuncAttributeMaxDynamicSharedMemorySize, GSM_TOTAL);
        cudaFuncSetAttribute(flash_k,   cudaFuncAttributeMaxDynamicSharedMemorySize, FSM_TOTAL);
        attr_done = true;
    }

    float *x, *t;
    __nv_bfloat16 *wqh,*wql,*wkh,*wkl,*wvh,*wvl,*woh,*wol,*w1h,*w1l,*w2h,*w2l;
    __nv_bfloat16 *xh,*xl,*qh,*ql,*kh,*kl,*vh,*vl,*ch,*cl,*hh,*hl;
    cudaGetSymbolAddress((void**)&x, g_x);
    cudaGetSymbolAddress((void**)&t, g_t);
    cudaGetSymbolAddress((void**)&wqh, g_wqh); cudaGetSymbolAddress((void**)&wql, g_wql);
    cudaGetSymbolAddress((void**)&wkh, g_wkh); cudaGetSymbolAddress((void**)&wkl, g_wkl);
    cudaGetSymbolAddress((void**)&wvh, g_wvh); cudaGetSymbolAddress((void**)&wvl, g_wvl);
    cudaGetSymbolAddress((void**)&woh, g_woh); cudaGetSymbolAddress((void**)&wol, g_wol);
    cudaGetSymbolAddress((void**)&w1h, g_w1h); cudaGetSymbolAddress((void**)&w1l, g_w1l);
    cudaGetSymbolAddress((void**)&w2h, g_w2h); cudaGetSymbolAddress((void**)&w2l, g_w2l);
    cudaGetSymbolAddress((void**)&xh, g_xh); cudaGetSymbolAddress((void**)&xl, g_xl);
    cudaGetSymbolAddress((void**)&qh, g_qh); cudaGetSymbolAddress((void**)&ql, g_ql);
    cudaGetSymbolAddress((void**)&kh, g_kh); cudaGetSymbolAddress((void**)&kl, g_kl);
    cudaGetSymbolAddress((void**)&vh, g_vh); cudaGetSymbolAddress((void**)&vl, g_vl);
    cudaGetSymbolAddress((void**)&ch, g_ch); cudaGetSymbolAddress((void**)&cl, g_cl);
    cudaGetSymbolAddress((void**)&hh, g_hh); cudaGetSymbolAddress((void**)&hl, g_hl);

    cudaMemcpyAsync(x, x_in, (size_t)SEQ * DM * sizeof(float),
                    cudaMemcpyDeviceToDevice, 0);

    // one-time (per call) weight + input splits
    const int WN4  = NL * DM * DM  / 4;
    const int WF4  = NL * DM * DFF / 4;
    const int XN4  = SEQ * DM / 4;
    split_k<<<(WN4+255)/256,256>>>(wq, wqh, wql, WN4);
    split_k<<<(WN4+255)/256,256>>>(wk, wkh, wkl, WN4);
    split_k<<<(WN4+255)/256,256>>>(wv, wvh, wvl, WN4);
    split_k<<<(WN4+255)/256,256>>>(wo, woh, wol, WN4);
    split_k<<<(WF4+255)/256,256>>>(w1, w1h, w1l, WF4);
    split_k<<<(WF4+255)/256,256>>>(w2, w2h, w2l, WF4);
    split_k<<<(XN4+255)/256,256>>>(x_in, xh, xl, XN4);

    dim3 gP(DM / 128, SEQ / 128);
    dim3 gF1(DFF / 128, SEQ / 128);
    dim3 gAtt(SEQ / 128, NH);

    for (int l = 0; l < NL; l++) {
        const __nv_bfloat16 *Wqh = wqh + (size_t)l*DM*DM, *Wql = wql + (size_t)l*DM*DM;
        const __nv_bfloat16 *Wkh = wkh + (size_t)l*DM*DM, *Wkl = wkl + (size_t)l*DM*DM;
        const __nv_bfloat16 *Wvh = wvh + (size_t)l*DM*DM, *Wvl = wvl + (size_t)l*DM*DM;
        const __nv_bfloat16 *Woh = woh + (size_t)l*DM*DM, *Wol = wol + (size_t)l*DM*DM;
        const __nv_bfloat16 *W1h = w1h + (size_t)l*DM*DFF, *W1l = w1l + (size_t)l*DM*DFF;
        const __nv_bfloat16 *W2h = w2h + (size_t)l*DFF*DM, *W2l = w2l + (size_t)l*DFF*DM;
        const float *Bq = bq + (size_t)l*DM,  *Bk = bk + (size_t)l*DM;
        const float *Bv = bv + (size_t)l*DM,  *Bo = bo + (size_t)l*DM;
        const float *B1 = b1 + (size_t)l*DFF, *B2 = b2 + (size_t)l*DM;
        const float *G1 = ln1g + (size_t)l*DM, *Be1 = ln1b + (size_t)l*DM;
        const float *G2 = ln2g + (size_t)l*DM, *Be2 = ln2b + (size_t)l*DM;

        // QKV projections -> hi/lo only
        gemm_s<0><<<gP,256,GSM_TOTAL>>>(xh, xl, Wqh, Wql, Bq, nullptr, qh, ql, DM, DM);
        gemm_s<0><<<gP,256,GSM_TOTAL>>>(xh, xl, Wkh, Wkl, Bk, nullptr, kh, kl, DM, DM);
        gemm_s<0><<<gP,256,GSM_TOTAL>>>(xh, xl, Wvh, Wvl, Bv, nullptr, vh, vl, DM, DM);
        // fused attention -> ctx hi/lo
        flash_k<<<gAtt,256,FSM_TOTAL>>>(qh, ql, kh, kl, vh, vl, ch, cl);
        // attn_out = ctx @ Wo + bo (fp32 only)
        gemm_s<0><<<gP,256,GSM_TOTAL>>>(ch, cl, Woh, Wol, Bo, t, nullptr, nullptr, DM, DM);
        // x = LN1(x + attn_out), also split
        ln_k<<<SEQ,256>>>(x, t, G1, Be1, x, xh, xl);
        // h = gelu(x @ W1 + b1) -> hi/lo only
        gemm_s<1><<<gF1,256,GSM_TOTAL>>>(xh, xl, W1h, W1l, B1, nullptr, hh, hl, DFF, DM);
        // ffn_out = h @ W2 + b2 (fp32 only)
        gemm_s<0><<<gP,256,GSM_TOTAL>>>(hh, hl, W2h, W2l, B2, t, nullptr, nullptr, DM, DFF);
        // x = LN2(x + ffn_out); final layer -> d_out (no split needed)
        float* outp = (l == NL - 1) ? (float*)d_out : x;
        __nv_bfloat16* oh = (l == NL - 1) ? nullptr : xh;
        __nv_bfloat16* ol = (l == NL - 1) ? nullptr : xl;
        ln_k<<<SEQ,256>>>(x, t, G2, Be2, outp, oh, ol);
    }
}

// round 6
// speedup vs baseline: 3.7245x; 1.0410x over previous
#include <cuda_runtime.h>
#include <cuda_bf16.h>
#include <math.h>
#include <stdint.h>

// Problem constants
#define SEQ   2048
#define DM    1024
#define NH    16
#define DK    64
#define DFF   4096
#define NL    4
#define LN_EPS 1e-5f

// ---------------------------------------------------------------------------
// Scratch (static device globals: allocation-free kernel_launch)
// ---------------------------------------------------------------------------
__device__ __nv_bfloat16 g_wqkvh[(size_t)NL*DM*3*DM], g_wqkvl[(size_t)NL*DM*3*DM];
__device__ float         g_bqkv[NL*3*DM];
__device__ __nv_bfloat16 g_woh[NL*DM*DM],  g_wol[NL*DM*DM];
__device__ __nv_bfloat16 g_w1h[NL*DM*DFF], g_w1l[NL*DM*DFF];
__device__ __nv_bfloat16 g_w2h[NL*DFF*DM], g_w2l[NL*DFF*DM];
__device__ float g_x[SEQ*DM];
__device__ float g_t[SEQ*DM];
__device__ __nv_bfloat16 g_xh[SEQ*DM],  g_xl[SEQ*DM];
__device__ __nv_bfloat16 g_qkvh[(size_t)SEQ*3*DM], g_qkvl[(size_t)SEQ*3*DM];
__device__ __nv_bfloat16 g_cxh[SEQ*DM], g_cxl[SEQ*DM];
__device__ __nv_bfloat16 g_hh[SEQ*DFF], g_hl[SEQ*DFF];

// ---------------------------------------------------------------------------
// Helpers
// ---------------------------------------------------------------------------
__device__ __forceinline__ uint32_t smem_u32(const void* p) {
    return (uint32_t)__cvta_generic_to_shared(p);
}
__device__ __forceinline__ uint32_t packbf(float a, float b) {
    __nv_bfloat162 t = __floats2bfloat162_rn(a, b);
    return *reinterpret_cast<uint32_t*>(&t);
}
__device__ __forceinline__ float lores(float a) {
    return a - __bfloat162float(__float2bfloat16_rn(a));
}
__device__ __forceinline__ void cp16(uint32_t dst, const void* src) {
    asm volatile("cp.async.cg.shared.global [%0], [%1], 16;\n" :: "r"(dst), "l"(src));
}
__device__ __forceinline__ void cp_commit() {
    asm volatile("cp.async.commit_group;\n" ::);
}
template<int N>
__device__ __forceinline__ void cp_wait() {
    asm volatile("cp.async.wait_group %0;\n" :: "n"(N));
}
__device__ __forceinline__ void ldsm_x4(uint32_t* r, uint32_t addr) {
    asm volatile("ldmatrix.sync.aligned.m8n8.x4.shared.b16 {%0,%1,%2,%3}, [%4];\n"
                 : "=r"(r[0]), "=r"(r[1]), "=r"(r[2]), "=r"(r[3]) : "r"(addr));
}
__device__ __forceinline__ void ldsm_x4_t(uint32_t* r, uint32_t addr) {
    asm volatile("ldmatrix.sync.aligned.m8n8.x4.trans.shared.b16 {%0,%1,%2,%3}, [%4];\n"
                 : "=r"(r[0]), "=r"(r[1]), "=r"(r[2]), "=r"(r[3]) : "r"(addr));
}
__device__ __forceinline__ void mma_bf16(float* c, const uint32_t* a, const uint32_t* b) {
    asm volatile(
        "mma.sync.aligned.m16n8k16.row.col.f32.bf16.bf16.f32 "
        "{%0,%1,%2,%3}, {%4,%5,%6,%7}, {%8,%9}, {%0,%1,%2,%3};\n"
        : "+f"(c[0]), "+f"(c[1]), "+f"(c[2]), "+f"(c[3])
        : "r"(a[0]), "r"(a[1]), "r"(a[2]), "r"(a[3]), "r"(b[0]), "r"(b[1]));
}

// ---------------------------------------------------------------------------
// fp32 -> (bf16 hi, bf16 lo) elementwise split, float4-wide
// ---------------------------------------------------------------------------
__global__ __launch_bounds__(256)
void split_k(const float* __restrict__ s, __nv_bfloat16* __restrict__ hi,
             __nv_bfloat16* __restrict__ lo, int n4)
{
    int i = blockIdx.x * 256 + threadIdx.x;
    if (i >= n4) return;
    float4 v = ((const float4*)s)[i];
    uint32_t* H = (uint32_t*)hi;
    uint32_t* L = (uint32_t*)lo;
    H[i*2]   = packbf(v.x, v.y);
    H[i*2+1] = packbf(v.z, v.w);
    L[i*2]   = packbf(lores(v.x), lores(v.y));
    L[i*2+1] = packbf(lores(v.z), lores(v.w));
}

// ---------------------------------------------------------------------------
// Pack Wq|Wk|Wv ([L,DM,DM] each) into [L, DM, 3*DM] hi/lo splits
// ---------------------------------------------------------------------------
__global__ __launch_bounds__(256)
void packqkv_k(const float* __restrict__ wq, const float* __restrict__ wk,
               const float* __restrict__ wv, __nv_bfloat16* __restrict__ H,
               __nv_bfloat16* __restrict__ L)
{
    size_t i4 = (size_t)blockIdx.x * 256 + threadIdx.x;
    const size_t total4 = (size_t)NL * DM * 3 * DM / 4;
    if (i4 >= total4) return;
    size_t e = i4 * 4;
    int j = (int)(e % (3 * DM));
    size_t rowl = e / (3 * DM);           // l*DM + k
    int s = j / DM, c = j % DM;           // same source for all 4 (DM%4==0)
    const float* src = (s == 0) ? wq : ((s == 1) ? wk : wv);
    float4 v = *(const float4*)&src[rowl * DM + c];
    uint32_t* Hp = (uint32_t*)H;
    uint32_t* Lp = (uint32_t*)L;
    Hp[i4*2]   = packbf(v.x, v.y);
    Hp[i4*2+1] = packbf(v.z, v.w);
    Lp[i4*2]   = packbf(lores(v.x), lores(v.y));
    Lp[i4*2+1] = packbf(lores(v.z), lores(v.w));
}

__global__ __launch_bounds__(256)
void packbias_k(const float* __restrict__ bq, const float* __restrict__ bk,
                const float* __restrict__ bv, float* __restrict__ out)
{
    int i = blockIdx.x * 256 + threadIdx.x;
    if (i >= NL * 3 * DM) return;
    int l = i / (3 * DM), j = i % (3 * DM);
    int s = j / DM, c = j % DM;
    const float* src = (s == 0) ? bq : ((s == 1) ? bk : bv);
    out[i] = src[l * DM + c];
}

// ---------------------------------------------------------------------------
// Pipelined bf16x3 tensor-core GEMM on pre-split inputs:
//   C = act( A @ B + bias ),  A: [M,K] hi/lo bf16 rm, B: [K,N] hi/lo bf16 rm.
// Outputs (each optional): Cf fp32, (Ch,Cl) bf16 hi/lo split of the result.
// Tile 128x128x32, 8 warps (2x4), warp tile 64x32.
// 4-stage cp.async pipeline, lead 3, ONE __syncthreads per K-iter.
// smem strides: A rows 40 elems (80B), B rows 136 elems (272B).
// ---------------------------------------------------------------------------
#define GSM_STAGE 37888
#define GSM_TOTAL (4 * GSM_STAGE)

template<int ACT>
__global__ __launch_bounds__(256, 1)
void gemm_s(const __nv_bfloat16* __restrict__ Ahg, const __nv_bfloat16* __restrict__ Alg,
            const __nv_bfloat16* __restrict__ Bhg, const __nv_bfloat16* __restrict__ Blg,
            const float* __restrict__ bias,
            float* __restrict__ Cf, __nv_bfloat16* __restrict__ Ch,
            __nv_bfloat16* __restrict__ Cl, int N, int K)
{
    extern __shared__ char smem[];
    const int tid = threadIdx.x, lane = tid & 31, warp = tid >> 5;
    const int wm0 = (warp & 1) * 64, wn0 = (warp >> 1) * 32;
    const int bm0 = blockIdx.y * 128, bn0 = blockIdx.x * 128;

    auto Ah_s = [&](int s){ return (__nv_bfloat16*)(smem + s*GSM_STAGE); };
    auto Al_s = [&](int s){ return (__nv_bfloat16*)(smem + s*GSM_STAGE + 10240); };
    auto Bh_s = [&](int s){ return (__nv_bfloat16*)(smem + s*GSM_STAGE + 20480); };
    auto Bl_s = [&](int s){ return (__nv_bfloat16*)(smem + s*GSM_STAGE + 29184); };

    auto load_stage = [&](int s, int kt) {
        const int k0 = kt * 32;
        __nv_bfloat16 *ah = Ah_s(s), *al = Al_s(s), *bh = Bh_s(s), *bl = Bl_s(s);
#pragma unroll
        for (int p = 0; p < 2; p++) {
            int c = p * 256 + tid;
            int r = c >> 2, sg = c & 3;
            size_t go = (size_t)(bm0 + r) * K + k0 + sg * 8;
            cp16(smem_u32(ah + r*40 + sg*8), Ahg + go);
            cp16(smem_u32(al + r*40 + sg*8), Alg + go);
        }
#pragma unroll
        for (int p = 0; p < 2; p++) {
            int c = p * 256 + tid;
            int r = c >> 4, sg = c & 15;
            size_t go = (size_t)(k0 + r) * N + bn0 + sg * 8;
            cp16(smem_u32(bh + r*136 + sg*8), Bhg + go);
            cp16(smem_u32(bl + r*136 + sg*8), Blg + go);
        }
    };

    float acc[4][4][4];
#pragma unroll
    for (int i = 0; i < 4; i++)
#pragma unroll
        for (int j = 0; j < 4; j++)
#pragma unroll
            for (int q = 0; q < 4; q++) acc[i][j][q] = 0.f;

    const int KT = K / 32;
    load_stage(0, 0); cp_commit();
    load_stage(1, 1); cp_commit();
    load_stage(2, 2); cp_commit();

    for (int kt = 0; kt < KT; kt++) {
        cp_wait<2>();
        __syncthreads();   // stage kt arrived everywhere; also: all warps done with compute kt-1

        if (kt + 3 < KT) load_stage((kt + 3) & 3, kt + 3);
        cp_commit();

        const int s = kt & 3;
        const __nv_bfloat16 *ah = Ah_s(s), *al = Al_s(s), *bh = Bh_s(s), *bl = Bl_s(s);
#pragma unroll
        for (int kc = 0; kc < 2; kc++) {
            const int kb = kc * 16;
            uint32_t aH[4][4], aL[4][4];
#pragma unroll
            for (int mt = 0; mt < 4; mt++) {
                int row = wm0 + mt * 16 + (lane & 15);
                int ko  = kb + ((lane >> 4) << 3);
                ldsm_x4(aH[mt], smem_u32(ah + row*40 + ko));
                ldsm_x4(aL[mt], smem_u32(al + row*40 + ko));
            }
            uint32_t bH[4][2], bL[4][2];
#pragma unroll
            for (int np = 0; np < 2; np++) {
                int g  = lane >> 3;
                int rk = kb + (lane & 7) + ((g & 1) << 3);
                int nc = wn0 + np * 16 + ((g >> 1) << 3);
                uint32_t t4[4];
                ldsm_x4_t(t4, smem_u32(bh + rk*136 + nc));
                bH[2*np][0] = t4[0]; bH[2*np][1] = t4[1];
                bH[2*np+1][0] = t4[2]; bH[2*np+1][1] = t4[3];
                ldsm_x4_t(t4, smem_u32(bl + rk*136 + nc));
                bL[2*np][0] = t4[0]; bL[2*np][1] = t4[1];
                bL[2*np+1][0] = t4[2]; bL[2*np+1][1] = t4[3];
            }
            // 3 passes of 16 independent MMAs (max ILP between acc reuses)
#pragma unroll
            for (int mt = 0; mt < 4; mt++)
#pragma unroll
                for (int nt = 0; nt < 4; nt++)
                    mma_bf16(acc[mt][nt], aH[mt], bH[nt]);
#pragma unroll
            for (int mt = 0; mt < 4; mt++)
#pragma unroll
                for (int nt = 0; nt < 4; nt++)
                    mma_bf16(acc[mt][nt], aL[mt], bH[nt]);
#pragma unroll
            for (int mt = 0; mt < 4; mt++)
#pragma unroll
                for (int nt = 0; nt < 4; nt++)
                    mma_bf16(acc[mt][nt], aH[mt], bL[nt]);
        }
    }

    // epilogue
#pragma unroll
    for (int mt = 0; mt < 4; mt++) {
        int r0 = bm0 + wm0 + mt * 16 + (lane >> 2);
#pragma unroll
        for (int nt = 0; nt < 4; nt++) {
            int c = bn0 + wn0 + nt * 8 + (lane & 3) * 2;
            float b0 = bias[c], b1 = bias[c + 1];
            float v[4];
#pragma unroll
            for (int q = 0; q < 4; q++) {
                float x = acc[mt][nt][q] + ((q & 1) ? b1 : b0);
                if (ACT == 1) {
                    float tt = tanhf(0.7978845608028654f * (x + 0.044715f * x * x * x));
                    x = 0.5f * x * (1.f + tt);
                }
                v[q] = x;
            }
            size_t o0 = (size_t)r0 * N + c, o1 = (size_t)(r0 + 8) * N + c;
            if (Cf) {
                *(float2*)&Cf[o0] = make_float2(v[0], v[1]);
                *(float2*)&Cf[o1] = make_float2(v[2], v[3]);
            }
            if (Ch) {
                ((uint32_t*)Ch)[o0 >> 1] = packbf(v[0], v[1]);
                ((uint32_t*)Ch)[o1 >> 1] = packbf(v[2], v[3]);
                ((uint32_t*)Cl)[o0 >> 1] = packbf(lores(v[0]), lores(v[1]));
                ((uint32_t*)Cl)[o1 >> 1] = packbf(lores(v[2]), lores(v[3]));
            }
        }
    }
}

// ---------------------------------------------------------------------------
// Flash attention: per block = (q-block of 128 rows, head).
// Q/K/V read from the packed qkv activation [SEQ, 3*DM] (ldq = 3*DM).
// S = (Q K^T)/8 via bf16x3; online softmax; O += P V via bf16x3.
// ---------------------------------------------------------------------------
#define FSM_ARR   18432
#define FSM_KV0   (2 * FSM_ARR)
#define FSM_STAGE (4 * FSM_ARR)
#define FSM_TOTAL (FSM_KV0 + 2 * FSM_STAGE)

__global__ __launch_bounds__(256, 1)
void flash_k(const __nv_bfloat16* __restrict__ Qh, const __nv_bfloat16* __restrict__ Ql,
             const __nv_bfloat16* __restrict__ Kh, const __nv_bfloat16* __restrict__ Kl,
             const __nv_bfloat16* __restrict__ Vh, const __nv_bfloat16* __restrict__ Vl,
             __nv_bfloat16* __restrict__ Ch, __nv_bfloat16* __restrict__ Cl, int ldq)
{
    extern __shared__ char smem[];
    const int tid = threadIdx.x, lane = tid & 31, warp = tid >> 5;
    const int qb = blockIdx.x, head = blockIdx.y;
    const int col0 = head * DK;

    __nv_bfloat16* Qsh = (__nv_bfloat16*)smem;
    __nv_bfloat16* Qsl = (__nv_bfloat16*)(smem + FSM_ARR);
    auto Ksh = [&](int s){ return (__nv_bfloat16*)(smem + FSM_KV0 + s*FSM_STAGE); };
    auto Ksl = [&](int s){ return (__nv_bfloat16*)(smem + FSM_KV0 + s*FSM_STAGE + FSM_ARR); };
    auto Vsh = [&](int s){ return (__nv_bfloat16*)(smem + FSM_KV0 + s*FSM_STAGE + 2*FSM_ARR); };
    auto Vsl = [&](int s){ return (__nv_bfloat16*)(smem + FSM_KV0 + s*FSM_STAGE + 3*FSM_ARR); };

#pragma unroll
    for (int p = 0; p < 4; p++) {
        int c = p * 256 + tid;
        int r = c >> 3, sg = c & 7;
        size_t go = (size_t)(qb * 128 + r) * ldq + col0 + sg * 8;
        cp16(smem_u32(Qsh + r*72 + sg*8), Qh + go);
        cp16(smem_u32(Qsl + r*72 + sg*8), Ql + go);
    }
    auto load_kv = [&](int s, int t) {
#pragma unroll
        for (int p = 0; p < 4; p++) {
            int c = p * 256 + tid;
            int r = c >> 3, sg = c & 7;
            size_t go = (size_t)(t * 128 + r) * ldq + col0 + sg * 8;
            cp16(smem_u32(Ksh(s) + r*72 + sg*8), Kh + go);
            cp16(smem_u32(Ksl(s) + r*72 + sg*8), Kl + go);
            cp16(smem_u32(Vsh(s) + r*72 + sg*8), Vh + go);
            cp16(smem_u32(Vsl(s) + r*72 + sg*8), Vl + go);
        }
    };
    load_kv(0, 0);
    cp_commit();

    float oacc[8][4];
#pragma unroll
    for (int i = 0; i < 8; i++)
#pragma unroll
        for (int q = 0; q < 4; q++) oacc[i][q] = 0.f;
    float mrun[2] = {-INFINITY, -INFINITY};
    float lrun[2] = {0.f, 0.f};

    const int NT_KV = SEQ / 128;
    for (int t = 0; t < NT_KV; t++) {
        if (t + 1 < NT_KV) load_kv((t + 1) & 1, t + 1);
        cp_commit();
        cp_wait<1>();
        __syncthreads();

        const int s = t & 1;
        const __nv_bfloat16 *ksh = Ksh(s), *ksl = Ksl(s), *vsh = Vsh(s), *vsl = Vsl(s);

        float sacc[16][4];
#pragma unroll
        for (int i = 0; i < 16; i++)
#pragma unroll
            for (int q = 0; q < 4; q++) sacc[i][q] = 0.f;

#pragma unroll
        for (int kc = 0; kc < 4; kc++) {
            const int kb = kc * 16;
            uint32_t aH[4], aL[4];
            {
                int row = warp * 16 + (lane & 15);
                int ko  = kb + ((lane >> 4) << 3);
                ldsm_x4(aH, smem_u32(Qsh + row*72 + ko));
                ldsm_x4(aL, smem_u32(Qsl + row*72 + ko));
            }
#pragma unroll
            for (int np = 0; np < 8; np++) {
                int nrow = np * 16 + (lane & 7) + ((lane >> 4) << 3);
                int kbase = kb + (((lane >> 3) & 1) << 3);
                uint32_t bh4[4], bl4[4];
                ldsm_x4(bh4, smem_u32(ksh + nrow*72 + kbase));
                ldsm_x4(bl4, smem_u32(ksl + nrow*72 + kbase));
                mma_bf16(sacc[2*np],   aH, bh4);
                mma_bf16(sacc[2*np],   aL, bh4);
                mma_bf16(sacc[2*np],   aH, bl4);
                mma_bf16(sacc[2*np+1], aH, bh4 + 2);
                mma_bf16(sacc[2*np+1], aL, bh4 + 2);
                mma_bf16(sacc[2*np+1], aH, bl4 + 2);
            }
        }

        float mnew[2];
#pragma unroll
        for (int rr = 0; rr < 2; rr++) {
            float m = -INFINITY;
#pragma unroll
            for (int nt = 0; nt < 16; nt++) {
                sacc[nt][2*rr]   *= 0.125f;
                sacc[nt][2*rr+1] *= 0.125f;
                m = fmaxf(m, fmaxf(sacc[nt][2*rr], sacc[nt][2*rr+1]));
            }
            m = fmaxf(m, __shfl_xor_sync(0xffffffffu, m, 1));
            m = fmaxf(m, __shfl_xor_sync(0xffffffffu, m, 2));
            mnew[rr] = fmaxf(mrun[rr], m);
        }
        float sc0 = __expf(mrun[0] - mnew[0]);
        float sc1 = __expf(mrun[1] - mnew[1]);
        float ls0 = 0.f, ls1 = 0.f;
#pragma unroll
        for (int nt = 0; nt < 16; nt++) {
            float p0 = __expf(sacc[nt][0] - mnew[0]);
            float p1 = __expf(sacc[nt][1] - mnew[0]);
            float p2 = __expf(sacc[nt][2] - mnew[1]);
            float p3 = __expf(sacc[nt][3] - mnew[1]);
            sacc[nt][0] = p0; sacc[nt][1] = p1; sacc[nt][2] = p2; sacc[nt][3] = p3;
            ls0 += p0 + p1; ls1 += p2 + p3;
        }
        ls0 += __shfl_xor_sync(0xffffffffu, ls0, 1);
        ls0 += __shfl_xor_sync(0xffffffffu, ls0, 2);
        ls1 += __shfl_xor_sync(0xffffffffu, ls1, 1);
        ls1 += __shfl_xor_sync(0xffffffffu, ls1, 2);
        lrun[0] = lrun[0] * sc0 + ls0;
        lrun[1] = lrun[1] * sc1 + ls1;
        mrun[0] = mnew[0]; mrun[1] = mnew[1];
#pragma unroll
        for (int nt = 0; nt < 8; nt++) {
            oacc[nt][0] *= sc0; oacc[nt][1] *= sc0;
            oacc[nt][2] *= sc1; oacc[nt][3] *= sc1;
        }

#pragma unroll
        for (int kt = 0; kt < 8; kt++) {
            uint32_t pH[4], pL[4];
            pH[0] = packbf(sacc[2*kt][0],   sacc[2*kt][1]);
            pH[1] = packbf(sacc[2*kt][2],   sacc[2*kt][3]);
            pH[2] = packbf(sacc[2*kt+1][0], sacc[2*kt+1][1]);
            pH[3] = packbf(sacc[2*kt+1][2], sacc[2*kt+1][3]);
            pL[0] = packbf(lores(sacc[2*kt][0]),   lores(sacc[2*kt][1]));
            pL[1] = packbf(lores(sacc[2*kt][2]),   lores(sacc[2*kt][3]));
            pL[2] = packbf(lores(sacc[2*kt+1][0]), lores(sacc[2*kt+1][1]));
            pL[3] = packbf(lores(sacc[2*kt+1][2]), lores(sacc[2*kt+1][3]));
#pragma unroll
            for (int np = 0; np < 4; np++) {
                int g  = lane >> 3;
                int rk = kt * 16 + (lane & 7) + ((g & 1) << 3);
                int nc = np * 16 + ((g >> 1) << 3);
                uint32_t bh4[4], bl4[4];
                ldsm_x4_t(bh4, smem_u32(vsh + rk*72 + nc));
                ldsm_x4_t(bl4, smem_u32(vsl + rk*72 + nc));
                mma_bf16(oacc[2*np],   pH, bh4);
                mma_bf16(oacc[2*np],   pL, bh4);
                mma_bf16(oacc[2*np],   pH, bl4);
                mma_bf16(oacc[2*np+1], pH, bh4 + 2);
                mma_bf16(oacc[2*np+1], pL, bh4 + 2);
                mma_bf16(oacc[2*np+1], pH, bl4 + 2);
            }
        }
        __syncthreads();
    }

    float inv0 = 1.f / lrun[0], inv1 = 1.f / lrun[1];
    int r0 = qb * 128 + warp * 16 + (lane >> 2);
#pragma unroll
    for (int nt = 0; nt < 8; nt++) {
        int c = col0 + nt * 8 + (lane & 3) * 2;
        float v0 = oacc[nt][0] * inv0, v1 = oacc[nt][1] * inv0;
        float v2 = oacc[nt][2] * inv1, v3 = oacc[nt][3] * inv1;
        size_t o0 = (size_t)r0 * DM + c, o1 = (size_t)(r0 + 8) * DM + c;
        ((uint32_t*)Ch)[o0 >> 1] = packbf(v0, v1);
        ((uint32_t*)Ch)[o1 >> 1] = packbf(v2, v3);
        ((uint32_t*)Cl)[o0 >> 1] = packbf(lores(v0), lores(v1));
        ((uint32_t*)Cl)[o1 >> 1] = packbf(lores(v2), lores(v3));
    }
}

// ---------------------------------------------------------------------------
// Fused residual + LayerNorm (1024): out = LN(x+sub)*g + b, plus hi/lo split
// ---------------------------------------------------------------------------
__global__ __launch_bounds__(256)
void ln_k(const float* __restrict__ x, const float* __restrict__ sub,
          const float* __restrict__ g, const float* __restrict__ b,
          float* __restrict__ out, __nv_bfloat16* __restrict__ oh,
          __nv_bfloat16* __restrict__ ol)
{
    const int tid = threadIdx.x;
    const size_t base = (size_t)blockIdx.x * DM + tid * 4;

    float4 xv = *(const float4*)(x + base);
    float4 sv = *(const float4*)(sub + base);
    float v0 = xv.x + sv.x, v1 = xv.y + sv.y, v2 = xv.z + sv.z, v3 = xv.w + sv.w;

    __shared__ float red[256];
    red[tid] = v0 + v1 + v2 + v3; __syncthreads();
#pragma unroll
    for (int s = 128; s > 0; s >>= 1) {
        if (tid < s) red[tid] += red[tid + s];
        __syncthreads();
    }
    const float mu = red[0] * (1.f / DM);
    __syncthreads();

    const float d0 = v0 - mu, d1 = v1 - mu, d2 = v2 - mu, d3 = v3 - mu;
    red[tid] = d0*d0 + d1*d1 + d2*d2 + d3*d3; __syncthreads();
#pragma unroll
    for (int s = 128; s > 0; s >>= 1) {
        if (tid < s) red[tid] += red[tid + s];
        __syncthreads();
    }
    const float inv = rsqrtf(red[0] * (1.f / DM) + LN_EPS);

    float4 gv = *(const float4*)(g + tid * 4);
    float4 bv = *(const float4*)(b + tid * 4);
    float o0 = d0 * inv * gv.x + bv.x;
    float o1 = d1 * inv * gv.y + bv.y;
    float o2 = d2 * inv * gv.z + bv.z;
    float o3 = d3 * inv * gv.w + bv.w;
    *(float4*)(out + base) = make_float4(o0, o1, o2, o3);
    if (oh) {
        ((uint32_t*)oh)[base >> 1]       = packbf(o0, o1);
        ((uint32_t*)oh)[(base >> 1) + 1] = packbf(o2, o3);
        ((uint32_t*)ol)[base >> 1]       = packbf(lores(o0), lores(o1));
        ((uint32_t*)ol)[(base >> 1) + 1] = packbf(lores(o2), lores(o3));
    }
}

// ---------------------------------------------------------------------------
// Host launcher
// ---------------------------------------------------------------------------
extern "C" void kernel_launch(void* const* d_in, const int* in_sizes, int n_in,
                              void* d_out, int out_size)
{
    (void)in_sizes; (void)n_in; (void)out_size;

    const float* x_in = (const float*)d_in[0];
    const float* wq  = (const float*)d_in[1];
    const float* bq  = (const float*)d_in[2];
    const float* wk  = (const float*)d_in[3];
    const float* bk  = (const float*)d_in[4];
    const float* wv  = (const float*)d_in[5];
    const float* bv  = (const float*)d_in[6];
    const float* wo  = (const float*)d_in[7];
    const float* bo  = (const float*)d_in[8];
    const float* w1  = (const float*)d_in[9];
    const float* b1  = (const float*)d_in[10];
    const float* w2  = (const float*)d_in[11];
    const float* b2  = (const float*)d_in[12];
    const float* ln1g = (const float*)d_in[13];
    const float* ln1b = (const float*)d_in[14];
    const float* ln2g = (const float*)d_in[15];
    const float* ln2b = (const float*)d_in[16];

    static bool attr_done = false;
    if (!attr_done) {
        cudaFuncSetAttribute(gemm_s<0>, cudaFuncAttributeMaxDynamicSharedMemorySize, GSM_TOTAL);
        cudaFuncSetAttribute(gemm_s<1>, cudaFuncAttributeMaxDynamicSharedMemorySize, GSM_TOTAL);
        cudaFuncSetAttribute(flash_k,   cudaFuncAttributeMaxDynamicSharedMemorySize, FSM_TOTAL);
        attr_done = true;
    }

    float *x, *t, *bqkv;
    __nv_bfloat16 *wqkvh,*wqkvl,*woh,*wol,*w1h,*w1l,*w2h,*w2l;
    __nv_bfloat16 *xh,*xl,*qkvh,*qkvl,*cxh,*cxl,*hh,*hl;
    cudaGetSymbolAddress((void**)&x, g_x);
    cudaGetSymbolAddress((void**)&t, g_t);
    cudaGetSymbolAddress((void**)&bqkv, g_bqkv);
    cudaGetSymbolAddress((void**)&wqkvh, g_wqkvh); cudaGetSymbolAddress((void**)&wqkvl, g_wqkvl);
    cudaGetSymbolAddress((void**)&woh, g_woh);     cudaGetSymbolAddress((void**)&wol, g_wol);
    cudaGetSymbolAddress((void**)&w1h, g_w1h);     cudaGetSymbolAddress((void**)&w1l, g_w1l);
    cudaGetSymbolAddress((void**)&w2h, g_w2h);     cudaGetSymbolAddress((void**)&w2l, g_w2l);
    cudaGetSymbolAddress((void**)&xh, g_xh);       cudaGetSymbolAddress((void**)&xl, g_xl);
    cudaGetSymbolAddress((void**)&qkvh, g_qkvh);   cudaGetSymbolAddress((void**)&qkvl, g_qkvl);
    cudaGetSymbolAddress((void**)&cxh, g_cxh);     cudaGetSymbolAddress((void**)&cxl, g_cxl);
    cudaGetSymbolAddress((void**)&hh, g_hh);       cudaGetSymbolAddress((void**)&hl, g_hl);

    cudaMemcpyAsync(x, x_in, (size_t)SEQ * DM * sizeof(float),
                    cudaMemcpyDeviceToDevice, 0);

    // per-call weight prep
    const size_t QKV4 = (size_t)NL * DM * 3 * DM / 4;
    packqkv_k<<<(int)((QKV4 + 255) / 256), 256>>>(wq, wk, wv, wqkvh, wqkvl);
    packbias_k<<<(NL*3*DM + 255) / 256, 256>>>(bq, bk, bv, bqkv);
    const int WN4 = NL * DM * DM / 4;
    const int WF4 = NL * DM * DFF / 4;
    split_k<<<(WN4+255)/256,256>>>(wo, woh, wol, WN4);
    split_k<<<(WF4+255)/256,256>>>(w1, w1h, w1l, WF4);
    split_k<<<(WF4+255)/256,256>>>(w2, w2h, w2l, WF4);
    split_k<<<(SEQ*DM/4 + 255)/256,256>>>(x_in, xh, xl, SEQ*DM/4);

    dim3 gQKV(3*DM / 128, SEQ / 128);
    dim3 gP(DM / 128, SEQ / 128);
    dim3 gF1(DFF / 128, SEQ / 128);
    dim3 gAtt(SEQ / 128, NH);

    for (int l = 0; l < NL; l++) {
        const __nv_bfloat16 *Wqkvh = wqkvh + (size_t)l*DM*3*DM, *Wqkvl = wqkvl + (size_t)l*DM*3*DM;
        const __nv_bfloat16 *Woh = woh + (size_t)l*DM*DM,  *Wol = wol + (size_t)l*DM*DM;
        const __nv_bfloat16 *W1h = w1h + (size_t)l*DM*DFF, *W1l = w1l + (size_t)l*DM*DFF;
        const __nv_bfloat16 *W2h = w2h + (size_t)l*DFF*DM, *W2l = w2l + (size_t)l*DFF*DM;
        const float *Bqkv = bqkv + (size_t)l*3*DM;
        const float *Bo = bo + (size_t)l*DM;
        const float *B1 = b1 + (size_t)l*DFF, *B2 = b2 + (size_t)l*DM;
        const float *G1 = ln1g + (size_t)l*DM, *Be1 = ln1b + (size_t)l*DM;
        const float *G2 = ln2g + (size_t)l*DM, *Be2 = ln2b + (size_t)l*DM;

        // fused QKV projection: [SEQ,1024] @ [1024,3072] -> qkv hi/lo
        gemm_s<0><<<gQKV,256,GSM_TOTAL>>>(xh, xl, Wqkvh, Wqkvl, Bqkv,
                                          nullptr, qkvh, qkvl, 3*DM, DM);
        // fused attention (Q at col 0, K at col DM, V at col 2*DM of qkv)
        flash_k<<<gAtt,256,FSM_TOTAL>>>(qkvh, qkvl, qkvh + DM, qkvl + DM,
                                        qkvh + 2*DM, qkvl + 2*DM, cxh, cxl, 3*DM);
        // attn_out = ctx @ Wo + bo (fp32)
        gemm_s<0><<<gP,256,GSM_TOTAL>>>(cxh, cxl, Woh, Wol, Bo, t, nullptr, nullptr, DM, DM);
        // x = LN1(x + attn_out), also split
        ln_k<<<SEQ,256>>>(x, t, G1, Be1, x, xh, xl);
        // h = gelu(x @ W1 + b1) -> hi/lo
        gemm_s<1><<<gF1,256,GSM_TOTAL>>>(xh, xl, W1h, W1l, B1, nullptr, hh, hl, DFF, DM);
        // ffn_out = h @ W2 + b2 (fp32)
        gemm_s<0><<<gP,256,GSM_TOTAL>>>(hh, hl, W2h, W2l, B2, t, nullptr, nullptr, DM, DFF);
        // x = LN2(x + ffn_out); final layer -> d_out
        float* outp = (l == NL - 1) ? (float*)d_out : x;
        __nv_bfloat16* oh = (l == NL - 1) ? nullptr : xh;
        __nv_bfloat16* ol = (l == NL - 1) ? nullptr : xl;
        ln_k<<<SEQ,256>>>(x, t, G2, Be2, outp, oh, ol);
    }
}